// round 13
// baseline (speedup 1.0000x reference)
#include <cuda_runtime.h>
#include <cuda_fp16.h>
#include <math.h>

#define Mpts 16384
#define Dm   256
#define Kn   16
#define DFFm 1024

// fp16 GEMM: CTA 128x64, warp tile 32x32, TBK=64, 3 CTAs/SM, 3-stage pipeline
#define TBM 128
#define TBN 64
#define TBK 64
#define NSTG 3
#define TILE_A (TBM * TBK * 2)          // 16KB
#define TILE_B (TBN * TBK * 2)          // 8KB
#define STG_BYTES (TILE_A + TILE_B)     // 24KB
#define GEMM_SMEM (NSTG * STG_BYTES)    // 72KB
#define MAXCTA 444                      // 3 per SM x 148 SMs

// ---------------- scratch -----------------------------------------------
__device__ float  g_x   [Mpts * Dm];
__device__ __half g_xn  [Mpts * Dm];
__device__ __half g_q   [Mpts * Dm];
__device__ __half g_kv  [Mpts * 2 * Dm];
__device__ __half g_attn[Mpts * Dm];
__device__ __half g_h   [Mpts * DFFm];
__device__ __half g_fa  [Mpts * Dm];
__device__ __half g_fb  [Mpts * Dm];
__device__ __half g_wq  [2 * Dm * Dm];
__device__ __half g_wkv [2 * 2 * Dm * Dm];
__device__ __half g_wo  [2 * Dm * Dm];
__device__ __half g_w1  [2 * DFFm * Dm];
__device__ __half g_w2  [2 * Dm * DFFm];

__device__ __forceinline__ float gelu_tanh(float x) {
    float x3 = x * x * x;
    return 0.5f * x * (1.0f + tanhf(0.7978845608028654f * (x + 0.044715f * x3)));
}
__device__ __forceinline__ void mma_f16(float c[4], unsigned a0, unsigned a1,
                                        unsigned a2, unsigned a3,
                                        unsigned b0, unsigned b1) {
    asm volatile(
        "mma.sync.aligned.m16n8k16.row.col.f32.f16.f16.f32 "
        "{%0,%1,%2,%3},{%4,%5,%6,%7},{%8,%9},{%0,%1,%2,%3};"
        : "+f"(c[0]), "+f"(c[1]), "+f"(c[2]), "+f"(c[3])
        : "r"(a0), "r"(a1), "r"(a2), "r"(a3), "r"(b0), "r"(b1));
}
__device__ __forceinline__ void cp16(void* s, const void* g) {
    unsigned a = (unsigned)__cvta_generic_to_shared(s);
    asm volatile("cp.async.cg.shared.global [%0], [%1], 16;" :: "r"(a), "l"(g));
}
__device__ __forceinline__ void ldsm4(unsigned& r0, unsigned& r1, unsigned& r2,
                                      unsigned& r3, unsigned addr) {
    asm volatile("ldmatrix.sync.aligned.m8n8.x4.shared.b16 {%0,%1,%2,%3}, [%4];"
                 : "=r"(r0), "=r"(r1), "=r"(r2), "=r"(r3) : "r"(addr));
}

// ---------------- fused prep: fp16 convert both feats + LN1(feat_a) -------
__global__ void convln_kernel(const float* __restrict__ fa_in, const float* __restrict__ fb_in,
                              __half* __restrict__ fa, __half* __restrict__ fb,
                              const float* __restrict__ g, const float* __restrict__ b,
                              __half* __restrict__ xn) {
    int lane = threadIdx.x;
    int row  = blockIdx.x * 8 + threadIdx.y;
    int c0 = lane * 8;
    bool isA = row < Mpts;
    int r = isA ? row : row - Mpts;
    const float* src = (isA ? fa_in : fb_in) + (size_t)r * Dm + c0;
    float v[8];
    *(float4*)(v)     = *(const float4*)src;
    *(float4*)(v + 4) = *(const float4*)(src + 4);
    __half2 hh[4];
#pragma unroll
    for (int j = 0; j < 4; j++) hh[j] = __floats2half2_rn(v[2 * j], v[2 * j + 1]);
    *(uint4*)((isA ? fa : fb) + (size_t)r * Dm + c0) = *(uint4*)hh;

    if (isA) {
        float s = 0.f, q = 0.f;
#pragma unroll
        for (int j = 0; j < 8; j++) { s += v[j]; q = fmaf(v[j], v[j], q); }
#pragma unroll
        for (int o = 16; o; o >>= 1) {
            s += __shfl_xor_sync(0xffffffffu, s, o);
            q += __shfl_xor_sync(0xffffffffu, q, o);
        }
        float mean = s * (1.0f / Dm);
        float inv = rsqrtf(fmaf(-mean, mean, q * (1.0f / Dm)) + 1e-5f);
        float4 g1 = *(const float4*)(g + c0), g2 = *(const float4*)(g + c0 + 4);
        float4 b1 = *(const float4*)(b + c0), b2 = *(const float4*)(b + c0 + 4);
        float gg[8] = {g1.x, g1.y, g1.z, g1.w, g2.x, g2.y, g2.z, g2.w};
        float bb[8] = {b1.x, b1.y, b1.z, b1.w, b2.x, b2.y, b2.z, b2.w};
        __half2 o4[4];
#pragma unroll
        for (int j = 0; j < 4; j++) {
            float o0 = (v[2 * j]     - mean) * inv * gg[2 * j]     + bb[2 * j];
            float o1 = (v[2 * j + 1] - mean) * inv * gg[2 * j + 1] + bb[2 * j + 1];
            o4[j] = __floats2half2_rn(o0, o1);
        }
        *(uint4*)(xn + (size_t)r * Dm + c0) = *(uint4*)o4;
    }
}

// ---------------- prep: all 6 weight transposes (one launch) --------------
__global__ void trnall(const float* __restrict__ Wq, const float* __restrict__ Wk,
                       const float* __restrict__ Wv, const float* __restrict__ Wo,
                       const float* __restrict__ W1, const float* __restrict__ W2,
                       __half* __restrict__ wq, __half* __restrict__ wkv,
                       __half* __restrict__ wo, __half* __restrict__ w1,
                       __half* __restrict__ w2) {
    __shared__ float t[32][33];
    int bid = blockIdx.x;
    const float* W; __half* Wt; int Kd, N, n0, k0;
    if (bid < 512) {
        int w = bid >> 7, tt = bid & 127, z = tt >> 6, tile = tt & 63;
        Kd = 256; N = 256; n0 = (tile & 7) * 32; k0 = (tile >> 3) * 32;
        if (w == 0)      { W = Wq + z * 65536; Wt = wq + z * 65536; }
        else if (w == 1) { W = Wk + z * 65536; Wt = wkv + z * 131072; }
        else if (w == 2) { W = Wv + z * 65536; Wt = wkv + z * 131072 + 65536; }
        else             { W = Wo + z * 65536; Wt = wo + z * 65536; }
    } else if (bid < 1024) {
        int tt = bid - 512, z = tt >> 8, tile = tt & 255;
        Kd = 256; N = 1024; n0 = (tile & 31) * 32; k0 = (tile >> 5) * 32;
        W = W1 + z * 262144; Wt = w1 + z * 262144;
    } else {
        int tt = bid - 1024, z = tt >> 8, tile = tt & 255;
        Kd = 1024; N = 256; n0 = (tile & 7) * 32; k0 = (tile >> 3) * 32;
        W = W2 + z * 262144; Wt = w2 + z * 262144;
    }
    int tx = threadIdx.x, ty = threadIdx.y;
#pragma unroll
    for (int i = 0; i < 4; i++)
        t[ty + i * 8][tx] = W[(size_t)(k0 + ty + i * 8) * N + n0 + tx];
    __syncthreads();
#pragma unroll
    for (int i = 0; i < 4; i++)
        Wt[(size_t)(n0 + ty + i * 8) * Kd + k0 + tx] = __float2half_rn(t[tx][ty + i * 8]);
}

// ---------------- LayerNorm: single-pass, 2 rows per warp ----------------
__global__ void ln_kernel(const float* __restrict__ x, const float* __restrict__ g,
                          const float* __restrict__ b, __half* __restrict__ y) {
    int lane = threadIdx.x;
    int c0 = lane * 8;
    int row0 = (blockIdx.x * 8 + threadIdx.y) * 2;
    const float* xr0 = x + (size_t)row0 * Dm + c0;
    const float* xr1 = xr0 + Dm;
    float v0[8], v1[8];
    *(float4*)(v0)     = *(const float4*)xr0;
    *(float4*)(v0 + 4) = *(const float4*)(xr0 + 4);
    *(float4*)(v1)     = *(const float4*)xr1;
    *(float4*)(v1 + 4) = *(const float4*)(xr1 + 4);

    float s0 = 0.f, q0 = 0.f, s1 = 0.f, q1 = 0.f;
#pragma unroll
    for (int j = 0; j < 8; j++) {
        s0 += v0[j]; q0 = fmaf(v0[j], v0[j], q0);
        s1 += v1[j]; q1 = fmaf(v1[j], v1[j], q1);
    }
#pragma unroll
    for (int o = 16; o; o >>= 1) {
        s0 += __shfl_xor_sync(0xffffffffu, s0, o);
        q0 += __shfl_xor_sync(0xffffffffu, q0, o);
        s1 += __shfl_xor_sync(0xffffffffu, s1, o);
        q1 += __shfl_xor_sync(0xffffffffu, q1, o);
    }
    float m0 = s0 * (1.0f / Dm), m1 = s1 * (1.0f / Dm);
    float i0 = rsqrtf(fmaf(-m0, m0, q0 * (1.0f / Dm)) + 1e-5f);
    float i1 = rsqrtf(fmaf(-m1, m1, q1 * (1.0f / Dm)) + 1e-5f);

    float4 g1 = *(const float4*)(g + c0), g2 = *(const float4*)(g + c0 + 4);
    float4 b1 = *(const float4*)(b + c0), b2 = *(const float4*)(b + c0 + 4);
    float gg[8] = {g1.x, g1.y, g1.z, g1.w, g2.x, g2.y, g2.z, g2.w};
    float bb[8] = {b1.x, b1.y, b1.z, b1.w, b2.x, b2.y, b2.z, b2.w};

    __half2 o0[4], o1[4];
#pragma unroll
    for (int j = 0; j < 4; j++) {
        o0[j] = __floats2half2_rn((v0[2*j] - m0) * i0 * gg[2*j] + bb[2*j],
                                  (v0[2*j+1] - m0) * i0 * gg[2*j+1] + bb[2*j+1]);
        o1[j] = __floats2half2_rn((v1[2*j] - m1) * i1 * gg[2*j] + bb[2*j],
                                  (v1[2*j+1] - m1) * i1 * gg[2*j+1] + bb[2*j+1]);
    }
    *(uint4*)(y + (size_t)row0 * Dm + c0)       = *(uint4*)o0;
    *(uint4*)(y + (size_t)(row0 + 1) * Dm + c0) = *(uint4*)o1;
}

// ---------------- persistent fp16 GEMM, 128x64 CTA, 3 CTAs/SM ------------
// C[M,N] = A[M,K] @ Bt[N,K]^T. nxLog=log2(N/TBN), cptLog=log2(Kd/TBK).
// EPI: 0 plain(fp16) | 1 +res(fp32) | 2 gelu(.+bias)(fp16) | 3 +bias+res(fp32)
template <int EPI, typename OT>
__global__ void __launch_bounds__(256, 3)
gemm_f16(const __half* __restrict__ A, const __half* __restrict__ Bt,
         const float* __restrict__ bias, const float* __restrict__ res,
         OT* __restrict__ C, int N, int Kd,
         int totalTiles, int nxLog, int cptLog) {
    extern __shared__ char smem[];
    const unsigned sb = (unsigned)__cvta_generic_to_shared(smem);

    const int tid  = threadIdx.x;
    const int wid  = tid >> 5;
    const int lane = tid & 31;
    const int g    = lane >> 2;
    const int tig  = lane & 3;
    const int rbase = (wid >> 1) * 32;   // 4 warp-rows of 32
    const int cbase = (wid & 1) * 32;    // 2 warp-cols of 32

    const int r8  = lane & 7;
    const int sel = lane >> 3;
    const int aRowL = (sel & 1) * 8 + r8;
    const int aKsel = sel >> 1;
    const int bRowL = (sel >> 1) * 8 + r8;
    const int bKsel = sel & 1;
    const int aXor  = aRowL & 7;
    const int bXor  = bRowL & 7;

    const int P = gridDim.x;
    const int cpt = 1 << cptLog;
    const int myTiles = (totalTiles - blockIdx.x + P - 1) / P;
    const int myChunks = myTiles << cptLog;

    // one chunk = 128x64 A tile + 64x64 B tile (swizzled rows of 128B)
#define ISSUE(chunk, stg)                                                      \
    {                                                                          \
        int _c = (chunk);                                                      \
        if (_c < myChunks) {                                                   \
            int _t  = _c >> cptLog;                                            \
            int _k0 = (_c & (cpt - 1)) * TBK;                                  \
            int _gt = blockIdx.x + _t * P;                                     \
            int _tx = _gt & ((1 << nxLog) - 1), _ty = _gt >> nxLog;            \
            const __half* Ab = A  + (size_t)_ty * TBM * Kd + _k0;              \
            const __half* Bb = Bt + (size_t)_tx * TBN * Kd + _k0;              \
            char* Asb = smem + (stg) * STG_BYTES;                              \
            char* Bsb = Asb + TILE_A;                                          \
            _Pragma("unroll")                                                  \
            for (int i = 0; i < 4; i++) {                                      \
                int idx = i * 256 + tid;                                       \
                int row = idx >> 3, seg = idx & 7;                             \
                int ps  = seg ^ (row & 7);                                     \
                cp16(Asb + row * 128 + ps * 16, Ab + (size_t)row * Kd + seg * 8); \
            }                                                                  \
            _Pragma("unroll")                                                  \
            for (int i = 0; i < 2; i++) {                                      \
                int idx = i * 256 + tid;                                       \
                int row = idx >> 3, seg = idx & 7;                             \
                int ps  = seg ^ (row & 7);                                     \
                cp16(Bsb + row * 128 + ps * 16, Bb + (size_t)row * Kd + seg * 8); \
            }                                                                  \
        }                                                                      \
        asm volatile("cp.async.commit_group;");                                \
    }

    ISSUE(0, 0);
    ISSUE(1, 1);

    float acc[2][4][4] = {};

    for (int cc = 0; cc < myChunks; cc++) {
        asm volatile("cp.async.wait_group 1;");
        __syncthreads();
        int sNext = cc + 2 - ((cc + 2) / 3) * 3;
        ISSUE(cc + 2, sNext);

        unsigned asb = sb + (unsigned)((cc - (cc / 3) * 3) * STG_BYTES);
        unsigned bsb = asb + TILE_A;
#pragma unroll
        for (int ks = 0; ks < 4; ks++) {
            unsigned af[2][4], bf[4][2];
            const int apc = ((ks * 2 + aKsel) ^ aXor) * 16;
            const int bpc = ((ks * 2 + bKsel) ^ bXor) * 16;
#pragma unroll
            for (int mt = 0; mt < 2; mt++)
                ldsm4(af[mt][0], af[mt][1], af[mt][2], af[mt][3],
                      asb + (unsigned)((rbase + mt * 16 + aRowL) * 128 + apc));
#pragma unroll
            for (int np = 0; np < 2; np++)
                ldsm4(bf[2 * np][0], bf[2 * np][1], bf[2 * np + 1][0], bf[2 * np + 1][1],
                      bsb + (unsigned)((cbase + np * 16 + bRowL) * 128 + bpc));
#pragma unroll
            for (int mt = 0; mt < 2; mt++)
#pragma unroll
                for (int nt = 0; nt < 4; nt++)
                    mma_f16(acc[mt][nt], af[mt][0], af[mt][1], af[mt][2], af[mt][3],
                            bf[nt][0], bf[nt][1]);
        }

        if ((cc & (cpt - 1)) == cpt - 1) {
            int gt = blockIdx.x + (cc >> cptLog) * P;
            int tx = gt & ((1 << nxLog) - 1), ty = gt >> nxLog;
            const int gr0 = ty * TBM + rbase + g;
            const int gc0 = tx * TBN + cbase + 2 * tig;
#pragma unroll
            for (int mt = 0; mt < 2; mt++) {
#pragma unroll
                for (int half = 0; half < 2; half++) {
                    int row = gr0 + mt * 16 + half * 8;
                    size_t base = (size_t)row * N + gc0;
#pragma unroll
                    for (int nt = 0; nt < 4; nt++) {
                        size_t off = base + nt * 8;
                        float v0 = acc[mt][nt][half * 2 + 0];
                        float v1 = acc[mt][nt][half * 2 + 1];
                        if (EPI == 1) {
                            float2 r = *(const float2*)(res + off);
                            v0 += r.x; v1 += r.y;
                        } else if (EPI == 2) {
                            int c = gc0 + nt * 8;
                            v0 = gelu_tanh(v0 + bias[c]);
                            v1 = gelu_tanh(v1 + bias[c + 1]);
                        } else if (EPI == 3) {
                            int c = gc0 + nt * 8;
                            float2 r = *(const float2*)(res + off);
                            v0 += bias[c] + r.x;
                            v1 += bias[c + 1] + r.y;
                        }
                        if (sizeof(OT) == 2) {
                            __half2 o = __floats2half2_rn(v0, v1);
                            *(__half2*)((__half*)C + off) = o;
                        } else {
                            float2 o = {v0, v1};
                            *(float2*)((float*)C + off) = o;
                        }
                    }
                }
            }
#pragma unroll
            for (int mt = 0; mt < 2; mt++)
#pragma unroll
                for (int nt = 0; nt < 4; nt++)
#pragma unroll
                    for (int r = 0; r < 4; r++) acc[mt][nt][r] = 0.f;
        }
    }
#undef ISSUE
}

// ---------------- KNN attention: fp16 q/kv in, fp16 out ------------------
__global__ void attn_kernel(const __half* __restrict__ q, const __half* __restrict__ kv,
                            const float* __restrict__ coord_q, const float* __restrict__ coord_c,
                            const int* __restrict__ idx,
                            const float* __restrict__ pe_w, const float* __restrict__ pe_b,
                            __half* __restrict__ out) {
    __shared__ float s_pw[3 * Dm];
    __shared__ float s_pb[Dm];
    int tid = threadIdx.x;
    for (int i = tid; i < 3 * Dm; i += 256) s_pw[i] = pe_w[i];
    if (tid < Dm) s_pb[tid] = pe_b[tid];
    __syncthreads();

    int warp = tid >> 5, lane = tid & 31;
    int m  = blockIdx.x * 8 + warp;
    int c0 = lane * 8;

    float qv[8];
    {
        uint4 u = *(const uint4*)(q + (size_t)m * Dm + c0);
        const __half2* hp = (const __half2*)&u;
#pragma unroll
        for (int j = 0; j < 4; j++) {
            float2 f = __half22float2(hp[j]);
            qv[2 * j] = f.x; qv[2 * j + 1] = f.y;
        }
    }
    float cx = coord_q[m * 3 + 0], cy = coord_q[m * 3 + 1], cz = coord_q[m * 3 + 2];

    float pw0[8], pw1[8], pw2[8], pb[8];
#pragma unroll
    for (int j = 0; j < 8; j++) {
        int c = c0 + j;
        pw0[j] = s_pw[c]; pw1[j] = s_pw[Dm + c]; pw2[j] = s_pw[2 * Dm + c]; pb[j] = s_pb[c];
    }

    int ids[Kn];
#pragma unroll
    for (int kk = 0; kk < Kn; kk++) ids[kk] = idx[(size_t)m * Kn + kk];

    float sc[Kn];
#pragma unroll
    for (int kk = 0; kk < Kn; kk++) {
        int id = ids[kk];
        bool val = id >= 0;
        int ic = val ? id : 0;
        float rx = cx - coord_c[ic * 3 + 0];
        float ry = cy - coord_c[ic * 3 + 1];
        float rz = cz - coord_c[ic * 3 + 2];
        uint4 u = *(const uint4*)(kv + (size_t)ic * 512 + c0);
        const __half2* hp = (const __half2*)&u;
        float p = 0.f;
#pragma unroll
        for (int j = 0; j < 4; j++) {
            float2 f = __half22float2(hp[j]);
            float pe0 = fmaf(rx, pw0[2*j],   fmaf(ry, pw1[2*j],   fmaf(rz, pw2[2*j],   pb[2*j])));
            float pe1 = fmaf(rx, pw0[2*j+1], fmaf(ry, pw1[2*j+1], fmaf(rz, pw2[2*j+1], pb[2*j+1])));
            p = fmaf(qv[2*j],   f.x + pe0, p);
            p = fmaf(qv[2*j+1], f.y + pe1, p);
        }
        p += __shfl_xor_sync(0xffffffffu, p, 1);
        p += __shfl_xor_sync(0xffffffffu, p, 2);
        p += __shfl_xor_sync(0xffffffffu, p, 4);
        sc[kk] = val ? p * 0.125f : -1e9f;
    }

    float mx = sc[0];
#pragma unroll
    for (int kk = 1; kk < Kn; kk++) mx = fmaxf(mx, sc[kk]);
    float sum = 0.f;
#pragma unroll
    for (int kk = 0; kk < Kn; kk++) { sc[kk] = expf(sc[kk] - mx); sum += sc[kk]; }
    float inv = 1.0f / sum;

    float acc[8] = {};
#pragma unroll
    for (int kk = 0; kk < Kn; kk++) {
        int id = ids[kk];
        int ic = id >= 0 ? id : 0;
        float rx = cx - coord_c[ic * 3 + 0];
        float ry = cy - coord_c[ic * 3 + 1];
        float rz = cz - coord_c[ic * 3 + 2];
        uint4 u = *(const uint4*)(kv + (size_t)ic * 512 + 256 + c0);
        const __half2* hp = (const __half2*)&u;
        float w = sc[kk];
#pragma unroll
        for (int j = 0; j < 4; j++) {
            float2 f = __half22float2(hp[j]);
            float pe0 = fmaf(rx, pw0[2*j],   fmaf(ry, pw1[2*j],   fmaf(rz, pw2[2*j],   pb[2*j])));
            float pe1 = fmaf(rx, pw0[2*j+1], fmaf(ry, pw1[2*j+1], fmaf(rz, pw2[2*j+1], pb[2*j+1])));
            acc[2*j]   = fmaf(w, f.x + pe0, acc[2*j]);
            acc[2*j+1] = fmaf(w, f.y + pe1, acc[2*j+1]);
        }
    }
    __half2 o4[4];
#pragma unroll
    for (int j = 0; j < 4; j++)
        o4[j] = __floats2half2_rn(acc[2*j] * inv, acc[2*j+1] * inv);
    *(uint4*)(out + (size_t)m * Dm + c0) = *(uint4*)o4;
}

// ---------------- driver --------------------------------------------------
static inline int gmin(int a, int b) { return a < b ? a : b; }

extern "C" void kernel_launch(void* const* d_in, const int* in_sizes, int n_in,
                              void* d_out, int out_size) {
    (void)in_sizes; (void)n_in; (void)out_size;
    const float* feat_a  = (const float*)d_in[0];
    const float* coord_a = (const float*)d_in[1];
    const float* feat_b  = (const float*)d_in[2];
    const float* coord_b = (const float*)d_in[3];
    const float* Wq      = (const float*)d_in[4];
    const float* Wk      = (const float*)d_in[5];
    const float* Wv      = (const float*)d_in[6];
    const float* Wo      = (const float*)d_in[7];
    const float* ln1_g   = (const float*)d_in[8];
    const float* ln1_b   = (const float*)d_in[9];
    const float* pe_w    = (const float*)d_in[10];
    const float* pe_b    = (const float*)d_in[11];
    const float* ffn_w1  = (const float*)d_in[12];
    const float* ffn_b1  = (const float*)d_in[13];
    const float* ffn_w2  = (const float*)d_in[14];
    const float* ffn_b2  = (const float*)d_in[15];
    const float* ln2_g   = (const float*)d_in[16];
    const float* ln2_b   = (const float*)d_in[17];
    const int*   knn_a2a = (const int*)d_in[18];
    const int*   knn_a2b = (const int*)d_in[19];
    float* out = (float*)d_out;

    float* x;
    __half *xn, *q, *kv, *attn, *h, *fa, *fb, *wq, *wkv, *wo, *w1, *w2;
    cudaGetSymbolAddress((void**)&x,    g_x);
    cudaGetSymbolAddress((void**)&xn,   g_xn);
    cudaGetSymbolAddress((void**)&q,    g_q);
    cudaGetSymbolAddress((void**)&kv,   g_kv);
    cudaGetSymbolAddress((void**)&attn, g_attn);
    cudaGetSymbolAddress((void**)&h,    g_h);
    cudaGetSymbolAddress((void**)&fa,   g_fa);
    cudaGetSymbolAddress((void**)&fb,   g_fb);
    cudaGetSymbolAddress((void**)&wq,   g_wq);
    cudaGetSymbolAddress((void**)&wkv,  g_wkv);
    cudaGetSymbolAddress((void**)&wo,   g_wo);
    cudaGetSymbolAddress((void**)&w1,   g_w1);
    cudaGetSymbolAddress((void**)&w2,   g_w2);

    static bool init_done = false;
    static cudaStream_t s1;
    static cudaEvent_t ev[6];
    if (!init_done) {
        cudaFuncSetAttribute((const void*)gemm_f16<0, __half>, cudaFuncAttributeMaxDynamicSharedMemorySize, GEMM_SMEM);
        cudaFuncSetAttribute((const void*)gemm_f16<1, float>,  cudaFuncAttributeMaxDynamicSharedMemorySize, GEMM_SMEM);
        cudaFuncSetAttribute((const void*)gemm_f16<2, __half>, cudaFuncAttributeMaxDynamicSharedMemorySize, GEMM_SMEM);
        cudaFuncSetAttribute((const void*)gemm_f16<3, float>,  cudaFuncAttributeMaxDynamicSharedMemorySize, GEMM_SMEM);
        cudaStreamCreateWithFlags(&s1, cudaStreamNonBlocking);
        for (int i = 0; i < 6; i++) cudaEventCreateWithFlags(&ev[i], cudaEventDisableTiming);
        init_done = true;
    }
    cudaStream_t s0 = 0;

    dim3 lnb(32, 8);
    cudaEventRecord(ev[0], s0);
    cudaStreamWaitEvent(s1, ev[0], 0);
    convln_kernel<<<4096, lnb, 0, s0>>>(feat_a, feat_b, fa, fb, ln1_g, ln1_b, xn);
    dim3 tb(32, 8);
    trnall<<<1536, tb, 0, s1>>>(Wq, Wk, Wv, Wo, ffn_w1, ffn_w2, wq, wkv, wo, w1, w2);
    cudaEventRecord(ev[1], s1);
    cudaStreamWaitEvent(s0, ev[1], 0);

    // tiles (TBM=128, TBN=64): Q/Wo: 128x4=512; KV: 128x8=1024; F1: 128x16=2048; F2: 512
    const int tQ = 512, tKV = 1024, tF1 = 2048;
    const int pQ = gmin(tQ, MAXCTA), pKV = gmin(tKV, MAXCTA), pF1 = gmin(tF1, MAXCTA);

    for (int blk = 0; blk < 2; blk++) {
        const float*  xin = (blk == 0) ? feat_a : x;
        const __half* ctx = (blk == 0) ? fa : fb;
        const float*  cc  = (blk == 0) ? coord_a : coord_b;
        const int*    idx = (blk == 0) ? knn_a2a : knn_a2b;
        size_t woff = (size_t)blk * Dm * Dm;
        int ef = 2 + blk * 2;
        int ej = 3 + blk * 2;

        cudaEventRecord(ev[ef], s0);
        cudaStreamWaitEvent(s1, ev[ef], 0);
        gemm_f16<0, __half><<<pKV, 256, GEMM_SMEM, s1>>>(
            ctx, wkv + (size_t)blk * 2 * Dm * Dm, nullptr, nullptr,
            kv, 2 * Dm, Dm, tKV, 3, 2);

        if (blk > 0)
            ln_kernel<<<Mpts / 16, lnb, 0, s0>>>(xin, ln1_g + blk * Dm, ln1_b + blk * Dm, xn);
        gemm_f16<0, __half><<<pQ, 256, GEMM_SMEM, s0>>>(xn, wq + woff, nullptr, nullptr,
                                                        q, Dm, Dm, tQ, 2, 2);
        cudaEventRecord(ev[ej], s1);
        cudaStreamWaitEvent(s0, ev[ej], 0);

        attn_kernel<<<Mpts / 8, 256, 0, s0>>>(q, kv, coord_a, cc, idx,
                                              pe_w + (size_t)blk * 3 * Dm,
                                              pe_b + blk * Dm, attn);

        gemm_f16<1, float><<<pQ, 256, GEMM_SMEM, s0>>>(attn, wo + woff, nullptr, xin,
                                                       x, Dm, Dm, tQ, 2, 2);

        ln_kernel<<<Mpts / 16, lnb, 0, s0>>>(x, ln2_g + blk * Dm, ln2_b + blk * Dm, xn);
        gemm_f16<2, __half><<<pF1, 256, GEMM_SMEM, s0>>>(xn, w1 + (size_t)blk * Dm * DFFm,
                                                         ffn_b1 + blk * DFFm, nullptr,
                                                         h, DFFm, Dm, tF1, 4, 2);
        float* xo = (blk == 1) ? out : x;
        gemm_f16<3, float><<<pQ, 256, GEMM_SMEM, s0>>>(h, w2 + (size_t)blk * Dm * DFFm,
                                                       ffn_b2 + blk * Dm, x,
                                                       xo, Dm, DFFm, tQ, 2, 4);
    }
}

// round 14
// speedup vs baseline: 1.1784x; 1.1784x over previous
#include <cuda_runtime.h>
#include <cuda_fp16.h>
#include <math.h>

#define Mpts 16384
#define Dm   256
#define Kn   16
#define DFFm 1024

// fp16 GEMM: CTA 128x128, TBK=64, swizzled smem, 3-stage pipeline (round-12 proven)
#define TBM 128
#define TBN 128
#define TBK 64
#define NSTG 3
#define TILE_BYTES (TBM * TBK * 2)
#define STG_BYTES  (2 * TILE_BYTES)
#define GEMM_SMEM  (NSTG * STG_BYTES)
#define MAXCTA 296

// ---------------- scratch -----------------------------------------------
__device__ float  g_x   [Mpts * Dm];
__device__ __half g_xn  [Mpts * Dm];
__device__ __half g_q   [Mpts * Dm];
__device__ __half g_kv  [Mpts * 2 * Dm];
__device__ __half g_attn[Mpts * Dm];
__device__ __half g_h   [Mpts * DFFm];
__device__ __half g_fa  [Mpts * Dm];
__device__ __half g_fb  [Mpts * Dm];
__device__ __half g_wq  [2 * Dm * Dm];
__device__ __half g_wkv [2 * 2 * Dm * Dm];
__device__ __half g_wo  [2 * Dm * Dm];
__device__ __half g_w1  [2 * DFFm * Dm];
__device__ __half g_w2  [2 * Dm * DFFm];

__device__ __forceinline__ float gelu_tanh(float x) {
    float x3 = x * x * x;
    return 0.5f * x * (1.0f + tanhf(0.7978845608028654f * (x + 0.044715f * x3)));
}
__device__ __forceinline__ void mma_f16(float c[4], unsigned a0, unsigned a1,
                                        unsigned a2, unsigned a3,
                                        unsigned b0, unsigned b1) {
    asm volatile(
        "mma.sync.aligned.m16n8k16.row.col.f32.f16.f16.f32 "
        "{%0,%1,%2,%3},{%4,%5,%6,%7},{%8,%9},{%0,%1,%2,%3};"
        : "+f"(c[0]), "+f"(c[1]), "+f"(c[2]), "+f"(c[3])
        : "r"(a0), "r"(a1), "r"(a2), "r"(a3), "r"(b0), "r"(b1));
}
__device__ __forceinline__ void cp16(void* s, const void* g) {
    unsigned a = (unsigned)__cvta_generic_to_shared(s);
    asm volatile("cp.async.cg.shared.global [%0], [%1], 16;" :: "r"(a), "l"(g));
}
__device__ __forceinline__ void ldsm4(unsigned& r0, unsigned& r1, unsigned& r2,
                                      unsigned& r3, unsigned addr) {
    asm volatile("ldmatrix.sync.aligned.m8n8.x4.shared.b16 {%0,%1,%2,%3}, [%4];"
                 : "=r"(r0), "=r"(r1), "=r"(r2), "=r"(r3) : "r"(addr));
}

// ---------------- fused prep: fp16 convert both feats + LN1(feat_a) -------
__global__ void convln_kernel(const float* __restrict__ fa_in, const float* __restrict__ fb_in,
                              __half* __restrict__ fa, __half* __restrict__ fb,
                              const float* __restrict__ g, const float* __restrict__ b,
                              __half* __restrict__ xn) {
    int lane = threadIdx.x;
    int row  = blockIdx.x * 8 + threadIdx.y;
    int c0 = lane * 8;
    bool isA = row < Mpts;
    int r = isA ? row : row - Mpts;
    const float* src = (isA ? fa_in : fb_in) + (size_t)r * Dm + c0;
    float v[8];
    *(float4*)(v)     = *(const float4*)src;
    *(float4*)(v + 4) = *(const float4*)(src + 4);
    __half2 hh[4];
#pragma unroll
    for (int j = 0; j < 4; j++) hh[j] = __floats2half2_rn(v[2 * j], v[2 * j + 1]);
    *(uint4*)((isA ? fa : fb) + (size_t)r * Dm + c0) = *(uint4*)hh;

    if (isA) {
        float s = 0.f, q = 0.f;
#pragma unroll
        for (int j = 0; j < 8; j++) { s += v[j]; q = fmaf(v[j], v[j], q); }
#pragma unroll
        for (int o = 16; o; o >>= 1) {
            s += __shfl_xor_sync(0xffffffffu, s, o);
            q += __shfl_xor_sync(0xffffffffu, q, o);
        }
        float mean = s * (1.0f / Dm);
        float inv = rsqrtf(fmaf(-mean, mean, q * (1.0f / Dm)) + 1e-5f);
        float4 g1 = *(const float4*)(g + c0), g2 = *(const float4*)(g + c0 + 4);
        float4 b1 = *(const float4*)(b + c0), b2 = *(const float4*)(b + c0 + 4);
        float gg[8] = {g1.x, g1.y, g1.z, g1.w, g2.x, g2.y, g2.z, g2.w};
        float bb[8] = {b1.x, b1.y, b1.z, b1.w, b2.x, b2.y, b2.z, b2.w};
        __half2 o4[4];
#pragma unroll
        for (int j = 0; j < 4; j++) {
            float o0 = (v[2 * j]     - mean) * inv * gg[2 * j]     + bb[2 * j];
            float o1 = (v[2 * j + 1] - mean) * inv * gg[2 * j + 1] + bb[2 * j + 1];
            o4[j] = __floats2half2_rn(o0, o1);
        }
        *(uint4*)(xn + (size_t)r * Dm + c0) = *(uint4*)o4;
    }
}

// ---------------- prep: all 6 weight transposes (one launch) --------------
__global__ void trnall(const float* __restrict__ Wq, const float* __restrict__ Wk,
                       const float* __restrict__ Wv, const float* __restrict__ Wo,
                       const float* __restrict__ W1, const float* __restrict__ W2,
                       __half* __restrict__ wq, __half* __restrict__ wkv,
                       __half* __restrict__ wo, __half* __restrict__ w1,
                       __half* __restrict__ w2) {
    __shared__ float t[32][33];
    int bid = blockIdx.x;
    const float* W; __half* Wt; int Kd, N, n0, k0;
    if (bid < 512) {
        int w = bid >> 7, tt = bid & 127, z = tt >> 6, tile = tt & 63;
        Kd = 256; N = 256; n0 = (tile & 7) * 32; k0 = (tile >> 3) * 32;
        if (w == 0)      { W = Wq + z * 65536; Wt = wq + z * 65536; }
        else if (w == 1) { W = Wk + z * 65536; Wt = wkv + z * 131072; }
        else if (w == 2) { W = Wv + z * 65536; Wt = wkv + z * 131072 + 65536; }
        else             { W = Wo + z * 65536; Wt = wo + z * 65536; }
    } else if (bid < 1024) {
        int tt = bid - 512, z = tt >> 8, tile = tt & 255;
        Kd = 256; N = 1024; n0 = (tile & 31) * 32; k0 = (tile >> 5) * 32;
        W = W1 + z * 262144; Wt = w1 + z * 262144;
    } else {
        int tt = bid - 1024, z = tt >> 8, tile = tt & 255;
        Kd = 1024; N = 256; n0 = (tile & 7) * 32; k0 = (tile >> 3) * 32;
        W = W2 + z * 262144; Wt = w2 + z * 262144;
    }
    int tx = threadIdx.x, ty = threadIdx.y;
#pragma unroll
    for (int i = 0; i < 4; i++)
        t[ty + i * 8][tx] = W[(size_t)(k0 + ty + i * 8) * N + n0 + tx];
    __syncthreads();
#pragma unroll
    for (int i = 0; i < 4; i++)
        Wt[(size_t)(n0 + ty + i * 8) * Kd + k0 + tx] = __float2half_rn(t[tx][ty + i * 8]);
}

// ---------------- LayerNorm: single-pass, 2 rows per warp ----------------
__global__ void ln_kernel(const float* __restrict__ x, const float* __restrict__ g,
                          const float* __restrict__ b, __half* __restrict__ y) {
    int lane = threadIdx.x;
    int c0 = lane * 8;
    int row0 = (blockIdx.x * 8 + threadIdx.y) * 2;
    const float* xr0 = x + (size_t)row0 * Dm + c0;
    const float* xr1 = xr0 + Dm;
    float v0[8], v1[8];
    *(float4*)(v0)     = *(const float4*)xr0;
    *(float4*)(v0 + 4) = *(const float4*)(xr0 + 4);
    *(float4*)(v1)     = *(const float4*)xr1;
    *(float4*)(v1 + 4) = *(const float4*)(xr1 + 4);

    float s0 = 0.f, q0 = 0.f, s1 = 0.f, q1 = 0.f;
#pragma unroll
    for (int j = 0; j < 8; j++) {
        s0 += v0[j]; q0 = fmaf(v0[j], v0[j], q0);
        s1 += v1[j]; q1 = fmaf(v1[j], v1[j], q1);
    }
#pragma unroll
    for (int o = 16; o; o >>= 1) {
        s0 += __shfl_xor_sync(0xffffffffu, s0, o);
        q0 += __shfl_xor_sync(0xffffffffu, q0, o);
        s1 += __shfl_xor_sync(0xffffffffu, s1, o);
        q1 += __shfl_xor_sync(0xffffffffu, q1, o);
    }
    float m0 = s0 * (1.0f / Dm), m1 = s1 * (1.0f / Dm);
    float i0 = rsqrtf(fmaf(-m0, m0, q0 * (1.0f / Dm)) + 1e-5f);
    float i1 = rsqrtf(fmaf(-m1, m1, q1 * (1.0f / Dm)) + 1e-5f);

    float4 g1 = *(const float4*)(g + c0), g2 = *(const float4*)(g + c0 + 4);
    float4 b1 = *(const float4*)(b + c0), b2 = *(const float4*)(b + c0 + 4);
    float gg[8] = {g1.x, g1.y, g1.z, g1.w, g2.x, g2.y, g2.z, g2.w};
    float bb[8] = {b1.x, b1.y, b1.z, b1.w, b2.x, b2.y, b2.z, b2.w};

    __half2 o0[4], o1[4];
#pragma unroll
    for (int j = 0; j < 4; j++) {
        o0[j] = __floats2half2_rn((v0[2*j] - m0) * i0 * gg[2*j] + bb[2*j],
                                  (v0[2*j+1] - m0) * i0 * gg[2*j+1] + bb[2*j+1]);
        o1[j] = __floats2half2_rn((v1[2*j] - m1) * i1 * gg[2*j] + bb[2*j],
                                  (v1[2*j+1] - m1) * i1 * gg[2*j+1] + bb[2*j+1]);
    }
    *(uint4*)(y + (size_t)row0 * Dm + c0)       = *(uint4*)o0;
    *(uint4*)(y + (size_t)(row0 + 1) * Dm + c0) = *(uint4*)o1;
}

// ---------------- persistent fp16 GEMM (round-12 config) -----------------
template <int EPI, typename OT>
__global__ void __launch_bounds__(256, 2)
gemm_f16(const __half* __restrict__ A, const __half* __restrict__ Bt,
         const float* __restrict__ bias, const float* __restrict__ res,
         OT* __restrict__ C, int N, int Kd,
         int totalTiles, int nxLog, int cptLog) {
    extern __shared__ char smem[];
    const unsigned sb = (unsigned)__cvta_generic_to_shared(smem);

    const int tid  = threadIdx.x;
    const int wid  = tid >> 5;
    const int lane = tid & 31;
    const int g    = lane >> 2;
    const int tig  = lane & 3;
    const int rbase = (wid >> 2) * 64;
    const int cbase = (wid & 3) * 32;

    const int r8  = lane & 7;
    const int sel = lane >> 3;
    const int aRowL = (sel & 1) * 8 + r8;
    const int aKsel = sel >> 1;
    const int bRowL = (sel >> 1) * 8 + r8;
    const int bKsel = sel & 1;
    const int aXor  = aRowL & 7;
    const int bXor  = bRowL & 7;

    const int P = gridDim.x;
    const int cpt = 1 << cptLog;
    const int myTiles = (totalTiles - blockIdx.x + P - 1) / P;
    const int myChunks = myTiles << cptLog;

#define ISSUE(chunk, stg)                                                      \
    {                                                                          \
        int _c = (chunk);                                                      \
        if (_c < myChunks) {                                                   \
            int _t  = _c >> cptLog;                                            \
            int _k0 = (_c & (cpt - 1)) * TBK;                                  \
            int _gt = blockIdx.x + _t * P;                                     \
            int _tx = _gt & ((1 << nxLog) - 1), _ty = _gt >> nxLog;            \
            const __half* Ab = A  + (size_t)_ty * TBM * Kd + _k0;              \
            const __half* Bb = Bt + (size_t)_tx * TBN * Kd + _k0;              \
            char* Asb = smem + (stg) * STG_BYTES;                              \
            char* Bsb = Asb + TILE_BYTES;                                      \
            _Pragma("unroll")                                                  \
            for (int i = 0; i < 4; i++) {                                      \
                int idx = i * 256 + tid;                                       \
                int row = idx >> 3, seg = idx & 7;                             \
                int ps  = seg ^ (row & 7);                                     \
                cp16(Asb + row * 128 + ps * 16, Ab + (size_t)row * Kd + seg * 8); \
                cp16(Bsb + row * 128 + ps * 16, Bb + (size_t)row * Kd + seg * 8); \
            }                                                                  \
        }                                                                      \
        asm volatile("cp.async.commit_group;");                                \
    }

    ISSUE(0, 0);
    ISSUE(1, 1);

    float acc[4][4][4] = {};

    for (int cc = 0; cc < myChunks; cc++) {
        asm volatile("cp.async.wait_group 1;");
        __syncthreads();
        int sNext = cc + 2 - ((cc + 2) / 3) * 3;
        ISSUE(cc + 2, sNext);

        unsigned asb = sb + (unsigned)((cc - (cc / 3) * 3) * STG_BYTES);
        unsigned bsb = asb + TILE_BYTES;
#pragma unroll
        for (int ks = 0; ks < 4; ks++) {
            unsigned af[4][4], bf[4][2];
            const int apc = ((ks * 2 + aKsel) ^ aXor) * 16;
            const int bpc = ((ks * 2 + bKsel) ^ bXor) * 16;
#pragma unroll
            for (int mt = 0; mt < 4; mt++)
                ldsm4(af[mt][0], af[mt][1], af[mt][2], af[mt][3],
                      asb + (unsigned)((rbase + mt * 16 + aRowL) * 128 + apc));
#pragma unroll
            for (int np = 0; np < 2; np++)
                ldsm4(bf[2 * np][0], bf[2 * np][1], bf[2 * np + 1][0], bf[2 * np + 1][1],
                      bsb + (unsigned)((cbase + np * 16 + bRowL) * 128 + bpc));
#pragma unroll
            for (int mt = 0; mt < 4; mt++)
#pragma unroll
                for (int nt = 0; nt < 4; nt++)
                    mma_f16(acc[mt][nt], af[mt][0], af[mt][1], af[mt][2], af[mt][3],
                            bf[nt][0], bf[nt][1]);
        }

        if ((cc & (cpt - 1)) == cpt - 1) {
            int gt = blockIdx.x + (cc >> cptLog) * P;
            int tx = gt & ((1 << nxLog) - 1), ty = gt >> nxLog;
            const int gr0 = ty * TBM + rbase + g;
            const int gc0 = tx * TBN + cbase + 2 * tig;
#pragma unroll
            for (int mt = 0; mt < 4; mt++) {
#pragma unroll
                for (int half = 0; half < 2; half++) {
                    int row = gr0 + mt * 16 + half * 8;
                    size_t base = (size_t)row * N + gc0;
#pragma unroll
                    for (int nt = 0; nt < 4; nt++) {
                        size_t off = base + nt * 8;
                        float v0 = acc[mt][nt][half * 2 + 0];
                        float v1 = acc[mt][nt][half * 2 + 1];
                        if (EPI == 1) {
                            float2 r = *(const float2*)(res + off);
                            v0 += r.x; v1 += r.y;
                        } else if (EPI == 2) {
                            int c = gc0 + nt * 8;
                            v0 = gelu_tanh(v0 + bias[c]);
                            v1 = gelu_tanh(v1 + bias[c + 1]);
                        } else if (EPI == 3) {
                            int c = gc0 + nt * 8;
                            float2 r = *(const float2*)(res + off);
                            v0 += bias[c] + r.x;
                            v1 += bias[c + 1] + r.y;
                        }
                        if (sizeof(OT) == 2) {
                            __half2 o = __floats2half2_rn(v0, v1);
                            *(__half2*)((__half*)C + off) = o;
                        } else {
                            float2 o = {v0, v1};
                            *(float2*)((float*)C + off) = o;
                        }
                    }
                }
            }
#pragma unroll
            for (int mt = 0; mt < 4; mt++)
#pragma unroll
                for (int nt = 0; nt < 4; nt++)
#pragma unroll
                    for (int r = 0; r < 4; r++) acc[mt][nt][r] = 0.f;
        }
    }
#undef ISSUE
}

// ---------------- KNN attention: pe folded out of inner loops ------------
// p = q.k + rel.(q@pw) + q.pb ;  out = [sum(w.v) + pe(sum(w.rel))]/sum + pb
__global__ void attn_kernel(const __half* __restrict__ q, const __half* __restrict__ kv,
                            const float* __restrict__ coord_q, const float* __restrict__ coord_c,
                            const int* __restrict__ idx,
                            const float* __restrict__ pe_w, const float* __restrict__ pe_b,
                            __half* __restrict__ out) {
    __shared__ float s_pw[3 * Dm];
    __shared__ float s_pb[Dm];
    int tid = threadIdx.x;
    for (int i = tid; i < 3 * Dm; i += 256) s_pw[i] = pe_w[i];
    if (tid < Dm) s_pb[tid] = pe_b[tid];
    __syncthreads();

    int warp = tid >> 5, lane = tid & 31;
    int m  = blockIdx.x * 8 + warp;
    int c0 = lane * 8;

    float qv[8];
    {
        uint4 u = *(const uint4*)(q + (size_t)m * Dm + c0);
        const __half2* hp = (const __half2*)&u;
#pragma unroll
        for (int j = 0; j < 4; j++) {
            float2 f = __half22float2(hp[j]);
            qv[2 * j] = f.x; qv[2 * j + 1] = f.y;
        }
    }
    float cx = coord_q[m * 3 + 0], cy = coord_q[m * 3 + 1], cz = coord_q[m * 3 + 2];

    float pw0[8], pw1[8], pw2[8], pb[8];
#pragma unroll
    for (int j = 0; j < 8; j++) {
        int c = c0 + j;
        pw0[j] = s_pw[c]; pw1[j] = s_pw[Dm + c]; pw2[j] = s_pw[2 * Dm + c]; pb[j] = s_pb[c];
    }

    // precompute q-projections of pe weights (per head, reduced over 64 ch)
    float qpw0 = 0.f, qpw1 = 0.f, qpw2 = 0.f, qpb = 0.f;
#pragma unroll
    for (int j = 0; j < 8; j++) {
        qpw0 = fmaf(qv[j], pw0[j], qpw0);
        qpw1 = fmaf(qv[j], pw1[j], qpw1);
        qpw2 = fmaf(qv[j], pw2[j], qpw2);
        qpb  = fmaf(qv[j], pb[j],  qpb);
    }
#pragma unroll
    for (int o = 1; o <= 4; o <<= 1) {
        qpw0 += __shfl_xor_sync(0xffffffffu, qpw0, o);
        qpw1 += __shfl_xor_sync(0xffffffffu, qpw1, o);
        qpw2 += __shfl_xor_sync(0xffffffffu, qpw2, o);
        qpb  += __shfl_xor_sync(0xffffffffu, qpb,  o);
    }

    int ids[Kn];
#pragma unroll
    for (int kk = 0; kk < Kn; kk++) ids[kk] = idx[(size_t)m * Kn + kk];

    float sc[Kn];
#pragma unroll
    for (int kk = 0; kk < Kn; kk++) {
        int id = ids[kk];
        bool val = id >= 0;
        int ic = val ? id : 0;
        float rx = cx - coord_c[ic * 3 + 0];
        float ry = cy - coord_c[ic * 3 + 1];
        float rz = cz - coord_c[ic * 3 + 2];
        uint4 u = *(const uint4*)(kv + (size_t)ic * 512 + c0);
        const __half2* hp = (const __half2*)&u;
        float p = 0.f;
#pragma unroll
        for (int j = 0; j < 4; j++) {
            float2 f = __half22float2(hp[j]);
            p = fmaf(qv[2*j],   f.x, p);
            p = fmaf(qv[2*j+1], f.y, p);
        }
        p += __shfl_xor_sync(0xffffffffu, p, 1);
        p += __shfl_xor_sync(0xffffffffu, p, 2);
        p += __shfl_xor_sync(0xffffffffu, p, 4);
        p += fmaf(rx, qpw0, fmaf(ry, qpw1, fmaf(rz, qpw2, qpb)));
        sc[kk] = val ? p * 0.125f : -1e9f;
    }

    float mx = sc[0];
#pragma unroll
    for (int kk = 1; kk < Kn; kk++) mx = fmaxf(mx, sc[kk]);
    float sum = 0.f;
#pragma unroll
    for (int kk = 0; kk < Kn; kk++) { sc[kk] = expf(sc[kk] - mx); sum += sc[kk]; }
    float inv = 1.0f / sum;

    float acc[8] = {};
    float rbx = 0.f, rby = 0.f, rbz = 0.f;   // sum(w * rel)
#pragma unroll
    for (int kk = 0; kk < Kn; kk++) {
        int id = ids[kk];
        int ic = id >= 0 ? id : 0;
        float w = sc[kk];
        rbx = fmaf(w, cx - coord_c[ic * 3 + 0], rbx);
        rby = fmaf(w, cy - coord_c[ic * 3 + 1], rby);
        rbz = fmaf(w, cz - coord_c[ic * 3 + 2], rbz);
        uint4 u = *(const uint4*)(kv + (size_t)ic * 512 + 256 + c0);
        const __half2* hp = (const __half2*)&u;
#pragma unroll
        for (int j = 0; j < 4; j++) {
            float2 f = __half22float2(hp[j]);
            acc[2*j]   = fmaf(w, f.x, acc[2*j]);
            acc[2*j+1] = fmaf(w, f.y, acc[2*j+1]);
        }
    }
    rbx *= inv; rby *= inv; rbz *= inv;      // sum(norm_w * rel); sum(norm_w)=1
    __half2 o4[4];
#pragma unroll
    for (int j = 0; j < 4; j++) {
        float o0 = fmaf(acc[2*j],   inv,
                   fmaf(rbx, pw0[2*j],   fmaf(rby, pw1[2*j],   fmaf(rbz, pw2[2*j],   pb[2*j]))));
        float o1 = fmaf(acc[2*j+1], inv,
                   fmaf(rbx, pw0[2*j+1], fmaf(rby, pw1[2*j+1], fmaf(rbz, pw2[2*j+1], pb[2*j+1]))));
        o4[j] = __floats2half2_rn(o0, o1);
    }
    *(uint4*)(out + (size_t)m * Dm + c0) = *(uint4*)o4;
}

// ---------------- driver --------------------------------------------------
static inline int gmin(int a, int b) { return a < b ? a : b; }

extern "C" void kernel_launch(void* const* d_in, const int* in_sizes, int n_in,
                              void* d_out, int out_size) {
    (void)in_sizes; (void)n_in; (void)out_size;
    const float* feat_a  = (const float*)d_in[0];
    const float* coord_a = (const float*)d_in[1];
    const float* feat_b  = (const float*)d_in[2];
    const float* coord_b = (const float*)d_in[3];
    const float* Wq      = (const float*)d_in[4];
    const float* Wk      = (const float*)d_in[5];
    const float* Wv      = (const float*)d_in[6];
    const float* Wo      = (const float*)d_in[7];
    const float* ln1_g   = (const float*)d_in[8];
    const float* ln1_b   = (const float*)d_in[9];
    const float* pe_w    = (const float*)d_in[10];
    const float* pe_b    = (const float*)d_in[11];
    const float* ffn_w1  = (const float*)d_in[12];
    const float* ffn_b1  = (const float*)d_in[13];
    const float* ffn_w2  = (const float*)d_in[14];
    const float* ffn_b2  = (const float*)d_in[15];
    const float* ln2_g   = (const float*)d_in[16];
    const float* ln2_b   = (const float*)d_in[17];
    const int*   knn_a2a = (const int*)d_in[18];
    const int*   knn_a2b = (const int*)d_in[19];
    float* out = (float*)d_out;

    float* x;
    __half *xn, *q, *kv, *attn, *h, *fa, *fb, *wq, *wkv, *wo, *w1, *w2;
    cudaGetSymbolAddress((void**)&x,    g_x);
    cudaGetSymbolAddress((void**)&xn,   g_xn);
    cudaGetSymbolAddress((void**)&q,    g_q);
    cudaGetSymbolAddress((void**)&kv,   g_kv);
    cudaGetSymbolAddress((void**)&attn, g_attn);
    cudaGetSymbolAddress((void**)&h,    g_h);
    cudaGetSymbolAddress((void**)&fa,   g_fa);
    cudaGetSymbolAddress((void**)&fb,   g_fb);
    cudaGetSymbolAddress((void**)&wq,   g_wq);
    cudaGetSymbolAddress((void**)&wkv,  g_wkv);
    cudaGetSymbolAddress((void**)&wo,   g_wo);
    cudaGetSymbolAddress((void**)&w1,   g_w1);
    cudaGetSymbolAddress((void**)&w2,   g_w2);

    static bool init_done = false;
    static cudaStream_t s1;
    static cudaEvent_t ev[6];
    if (!init_done) {
        cudaFuncSetAttribute((const void*)gemm_f16<0, __half>, cudaFuncAttributeMaxDynamicSharedMemorySize, GEMM_SMEM);
        cudaFuncSetAttribute((const void*)gemm_f16<1, float>,  cudaFuncAttributeMaxDynamicSharedMemorySize, GEMM_SMEM);
        cudaFuncSetAttribute((const void*)gemm_f16<2, __half>, cudaFuncAttributeMaxDynamicSharedMemorySize, GEMM_SMEM);
        cudaFuncSetAttribute((const void*)gemm_f16<3, float>,  cudaFuncAttributeMaxDynamicSharedMemorySize, GEMM_SMEM);
        cudaStreamCreateWithFlags(&s1, cudaStreamNonBlocking);
        for (int i = 0; i < 6; i++) cudaEventCreateWithFlags(&ev[i], cudaEventDisableTiming);
        init_done = true;
    }
    cudaStream_t s0 = 0;

    dim3 lnb(32, 8);
    cudaEventRecord(ev[0], s0);
    cudaStreamWaitEvent(s1, ev[0], 0);
    convln_kernel<<<4096, lnb, 0, s0>>>(feat_a, feat_b, fa, fb, ln1_g, ln1_b, xn);
    dim3 tb(32, 8);
    trnall<<<1536, tb, 0, s1>>>(Wq, Wk, Wv, Wo, ffn_w1, ffn_w2, wq, wkv, wo, w1, w2);
    cudaEventRecord(ev[1], s1);
    cudaStreamWaitEvent(s0, ev[1], 0);

    const int tQ = 256, tKV = 512, tF1 = 1024;
    const int pQ = gmin(tQ, MAXCTA), pKV = gmin(tKV, MAXCTA), pF1 = gmin(tF1, MAXCTA);

    for (int blk = 0; blk < 2; blk++) {
        const float*  xin = (blk == 0) ? feat_a : x;
        const __half* ctx = (blk == 0) ? fa : fb;
        const float*  cc  = (blk == 0) ? coord_a : coord_b;
        const int*    idx = (blk == 0) ? knn_a2a : knn_a2b;
        size_t woff = (size_t)blk * Dm * Dm;
        int ef = 2 + blk * 2;
        int ej = 3 + blk * 2;

        cudaEventRecord(ev[ef], s0);
        cudaStreamWaitEvent(s1, ev[ef], 0);
        gemm_f16<0, __half><<<pKV, 256, GEMM_SMEM, s1>>>(
            ctx, wkv + (size_t)blk * 2 * Dm * Dm, nullptr, nullptr,
            kv, 2 * Dm, Dm, tKV, 2, 2);

        if (blk > 0)
            ln_kernel<<<Mpts / 16, lnb, 0, s0>>>(xin, ln1_g + blk * Dm, ln1_b + blk * Dm, xn);
        gemm_f16<0, __half><<<pQ, 256, GEMM_SMEM, s0>>>(xn, wq + woff, nullptr, nullptr,
                                                        q, Dm, Dm, tQ, 1, 2);
        cudaEventRecord(ev[ej], s1);
        cudaStreamWaitEvent(s0, ev[ej], 0);

        attn_kernel<<<Mpts / 8, 256, 0, s0>>>(q, kv, coord_a, cc, idx,
                                              pe_w + (size_t)blk * 3 * Dm,
                                              pe_b + blk * Dm, attn);

        gemm_f16<1, float><<<pQ, 256, GEMM_SMEM, s0>>>(attn, wo + woff, nullptr, xin,
                                                       x, Dm, Dm, tQ, 1, 2);

        ln_kernel<<<Mpts / 16, lnb, 0, s0>>>(x, ln2_g + blk * Dm, ln2_b + blk * Dm, xn);
        gemm_f16<2, __half><<<pF1, 256, GEMM_SMEM, s0>>>(xn, w1 + (size_t)blk * Dm * DFFm,
                                                         ffn_b1 + blk * DFFm, nullptr,
                                                         h, DFFm, Dm, tF1, 3, 2);
        float* xo = (blk == 1) ? out : x;
        gemm_f16<3, float><<<pQ, 256, GEMM_SMEM, s0>>>(h, w2 + (size_t)blk * Dm * DFFm,
                                                       ffn_b2 + blk * Dm, x,
                                                       xo, Dm, DFFm, tQ, 1, 4);
    }
}